// round 1
// baseline (speedup 1.0000x reference)
#include <cuda_runtime.h>
#include <math.h>

// ---------------- problem constants ----------------
#define BSZ   16
#define NIN   512
#define NTOK  513          // N_IN + 1
#define EDIM  768
#define NHEAD 12
#define HDIM  64
#define NLAY  12
#define FFDIM 3072
#define MTOT  (BSZ*NTOK)   // 8208
#define MX    (BSZ*NIN)    // 8192
#define LNEPS 1e-5f
#define POSTSCALE 27.712812921102035f   // sqrt(768), applied AFTER softmax

// ---------------- scratch (static device globals; no allocs allowed) ----
__device__ float g_h [(size_t)MTOT*EDIM];
__device__ float g_y [(size_t)MTOT*EDIM];
__device__ float g_q [(size_t)BSZ*NHEAD*NTOK*HDIM];
__device__ float g_k [(size_t)BSZ*NHEAD*NTOK*HDIM];
__device__ float g_v [(size_t)BSZ*NHEAD*NTOK*HDIM];
__device__ float g_o [(size_t)MTOT*EDIM];
__device__ float g_ff[(size_t)MTOT*FFDIM];

// ---------------- GEMM: C[M,Nn] = A[M,K] @ W[K,Nn] (+bias) (+epilogue) ----
// EPI: 0 = bias only, 1 = bias + residual add, 2 = bias + exact GELU,
//      3 = bias + scatter into q/k/v buffers (head-interleaved qkv layout)
template<int EPI>
__global__ __launch_bounds__(256) void gemm_k(
    const float* __restrict__ A, const float* __restrict__ W,
    const float* __restrict__ bias, const float* __restrict__ res,
    float* __restrict__ C, int M, int Nn, int K,
    float* __restrict__ qb, float* __restrict__ kb, float* __restrict__ vb)
{
    __shared__ float As[8][128];
    __shared__ float Bs[8][128];
    const int tid  = threadIdx.x;
    const int tcol = tid & 15;            // 0..15  (x within tile)
    const int trow = tid >> 4;            // 0..15  (y within tile)
    const int arow = tid >> 1;            // 0..127
    const int acol = (tid & 1) << 2;      // 0 or 4
    const int browl = tid >> 5;           // 0..7
    const int bcoll = (tid & 31) << 2;    // 0..124
    const long gArow = (long)blockIdx.y*128 + arow;
    const int  gBcol = blockIdx.x*128 + bcoll;

    float acc[8][8];
    #pragma unroll
    for (int i = 0; i < 8; i++)
        #pragma unroll
        for (int j = 0; j < 8; j++) acc[i][j] = 0.f;

    const float* Aptr = A + gArow*(long)K + acol;
    const float* Wptr = W + (long)browl*Nn + gBcol;
    const bool aok = (gArow < M);

    for (int k0 = 0; k0 < K; k0 += 8) {
        float4 a4 = make_float4(0.f,0.f,0.f,0.f);
        if (aok) a4 = *(const float4*)(Aptr + k0);
        As[acol+0][arow] = a4.x;
        As[acol+1][arow] = a4.y;
        As[acol+2][arow] = a4.z;
        As[acol+3][arow] = a4.w;
        float4 b4 = *(const float4*)(Wptr + (long)k0*Nn);
        *(float4*)&Bs[browl][bcoll] = b4;
        __syncthreads();
        #pragma unroll
        for (int kk = 0; kk < 8; kk++) {
            float ra[8], rb[8];
            #pragma unroll
            for (int i = 0; i < 8; i++) ra[i] = As[kk][trow*8+i];
            #pragma unroll
            for (int j = 0; j < 8; j++) rb[j] = Bs[kk][tcol*8+j];
            #pragma unroll
            for (int i = 0; i < 8; i++)
                #pragma unroll
                for (int j = 0; j < 8; j++)
                    acc[i][j] = fmaf(ra[i], rb[j], acc[i][j]);
        }
        __syncthreads();
    }

    #pragma unroll
    for (int i = 0; i < 8; i++) {
        long r = (long)blockIdx.y*128 + trow*8 + i;
        if (r >= M) continue;
        if (EPI == 3) {
            // qkv scatter: col c -> head hh=c/192, dim dd=(c/3)%64, which=c%3
            int b = (int)(r / NTOK), n = (int)(r % NTOK);
            #pragma unroll
            for (int j = 0; j < 8; j++) {
                int c = blockIdx.x*128 + tcol*8 + j;
                float val = acc[i][j] + bias[c];
                int which = c % 3;
                int hh = c / 192;
                int dd = (c / 3) & 63;
                long off = ((long)(b*NHEAD + hh)*NTOK + n)*HDIM + dd;
                if (which == 0)      qb[off] = val;
                else if (which == 1) kb[off] = val;
                else                 vb[off] = val;
            }
        } else {
            long base = r*(long)Nn + blockIdx.x*128 + tcol*8;
            #pragma unroll
            for (int j = 0; j < 8; j++) {
                int c = blockIdx.x*128 + tcol*8 + j;
                float val = acc[i][j] + bias[c];
                if (EPI == 1) val += res[base + j];
                if (EPI == 2) val = 0.5f*val*(1.0f + erff(val*0.7071067811865475f));
                C[base + j] = val;
            }
        }
    }
}

// ---------------- LayerNorm: one block per row ----------------
__global__ __launch_bounds__(256) void ln_k(
    const float* __restrict__ x, const float* __restrict__ g,
    const float* __restrict__ b, float* __restrict__ y)
{
    long row = blockIdx.x;
    const float* xr = x + row*(long)EDIM;
    int t = threadIdx.x;
    float v0 = xr[t], v1 = xr[t+256], v2 = xr[t+512];
    float s  = v0 + v1 + v2;
    float sq = v0*v0 + v1*v1 + v2*v2;
    #pragma unroll
    for (int o = 16; o > 0; o >>= 1) {
        s  += __shfl_xor_sync(0xffffffffu, s,  o);
        sq += __shfl_xor_sync(0xffffffffu, sq, o);
    }
    __shared__ float ss[8], sqs[8];
    __shared__ float mu_s, rs_s;
    if ((t & 31) == 0) { ss[t>>5] = s; sqs[t>>5] = sq; }
    __syncthreads();
    if (t == 0) {
        float S = 0.f, Q = 0.f;
        #pragma unroll
        for (int i = 0; i < 8; i++) { S += ss[i]; Q += sqs[i]; }
        float mu = S * (1.0f/EDIM);
        float var = Q * (1.0f/EDIM) - mu*mu;
        mu_s = mu;
        rs_s = rsqrtf(var + LNEPS);
    }
    __syncthreads();
    float mu = mu_s, rs = rs_s;
    float* yr = y + row*(long)EDIM;
    yr[t]     = (v0 - mu)*rs*g[t]     + b[t];
    yr[t+256] = (v1 - mu)*rs*g[t+256] + b[t+256];
    yr[t+512] = (v2 - mu)*rs*g[t+512] + b[t+512];
}

// ---------------- fused attention: 1 thread = 1 query row ----------------
__global__ __launch_bounds__(128) void attn_k(
    const float* __restrict__ q, const float* __restrict__ k,
    const float* __restrict__ v, float* __restrict__ o)
{
    const int bh = blockIdx.x;                 // b*NHEAD + hh
    const int qi = blockIdx.y*128 + threadIdx.x;
    const int b = bh / NHEAD, hh = bh % NHEAD;
    const long base = (long)bh*NTOK*HDIM;
    const bool act = (qi < NTOK);
    const int tid = threadIdx.x;

    float qr[64];
    if (act) {
        const float4* qp = (const float4*)(q + base + (long)qi*HDIM);
        #pragma unroll
        for (int i = 0; i < 16; i++) {
            float4 t4 = qp[i];
            qr[4*i] = t4.x; qr[4*i+1] = t4.y; qr[4*i+2] = t4.z; qr[4*i+3] = t4.w;
        }
    }
    float m = -3.0e38f, l = 0.f, acc[64];
    #pragma unroll
    for (int d = 0; d < 64; d++) acc[d] = 0.f;

    __shared__ float Ks[32][64];
    __shared__ float Vs[32][64];

    for (int kb = 0; kb < NTOK; kb += 32) {
        int nk = NTOK - kb; if (nk > 32) nk = 32;
        __syncthreads();
        #pragma unroll
        for (int i = 0; i < 4; i++) {
            int idx = i*512 + tid*4;
            int row = idx >> 6, col = idx & 63;
            if (row < nk) {
                *(float4*)&Ks[row][col] = *(const float4*)(k + base + (long)(kb+row)*HDIM + col);
                *(float4*)&Vs[row][col] = *(const float4*)(v + base + (long)(kb+row)*HDIM + col);
            }
        }
        __syncthreads();
        if (act) {
            for (int kk = 0; kk < nk; kk++) {
                float s = 0.f;
                #pragma unroll
                for (int d = 0; d < 64; d++) s = fmaf(qr[d], Ks[kk][d], s);
                if (s > m) {
                    float c = __expf(m - s);
                    l = l*c + 1.f;
                    #pragma unroll
                    for (int d = 0; d < 64; d++) acc[d] = acc[d]*c + Vs[kk][d];
                    m = s;
                } else {
                    float e = __expf(s - m);
                    l += e;
                    #pragma unroll
                    for (int d = 0; d < 64; d++) acc[d] = fmaf(e, Vs[kk][d], acc[d]);
                }
            }
        }
    }
    if (act) {
        float inv = 1.f / (l * POSTSCALE);       // softmax normalize + post-scale
        float* op = o + ((long)(b*NTOK) + qi)*EDIM + hh*HDIM;
        #pragma unroll
        for (int i = 0; i < 16; i++) {
            float4 t4 = make_float4(acc[4*i]*inv, acc[4*i+1]*inv,
                                    acc[4*i+2]*inv, acc[4*i+3]*inv);
            *(float4*)(op + 4*i) = t4;
        }
    }
}

// ---------------- embed: h[b,n,:] = (n==0 ? cls : xproj[b,n-1]) + pos[n] ----
__global__ void embed_k(const float* __restrict__ t, const float* __restrict__ cls,
                        const float* __restrict__ pos, float* __restrict__ h)
{
    long idx = (long)blockIdx.x*blockDim.x + threadIdx.x;
    if (idx >= (long)MTOT*EDIM) return;
    int e = (int)(idx % EDIM);
    long row = idx / EDIM;
    int b = (int)(row / NTOK), n = (int)(row % NTOK);
    float base = (n == 0) ? cls[e] : t[((long)b*NIN + (n-1))*EDIM + e];
    h[idx] = base + pos[(long)n*EDIM + e];
}

// ---------------- output: CLS token rows ----------------
__global__ void out_k(const float* __restrict__ h, float* __restrict__ out)
{
    int i = blockIdx.x*blockDim.x + threadIdx.x;
    if (i >= BSZ*EDIM) return;
    int b = i / EDIM, e = i % EDIM;
    out[i] = h[(long)b*NTOK*EDIM + e];
}

// ---------------- host launcher ----------------
extern "C" void kernel_launch(void* const* d_in, const int* in_sizes, int n_in,
                              void* d_out, int out_size)
{
    const float* x      = (const float*)d_in[0];
    const float* proj_w = (const float*)d_in[1];
    const float* proj_b = (const float*)d_in[2];
    const float* cls    = (const float*)d_in[3];
    const float* pos    = (const float*)d_in[4];
    const float* ln1_g  = (const float*)d_in[5];
    const float* ln1_b  = (const float*)d_in[6];
    const float* qkv_w  = (const float*)d_in[7];
    const float* qkv_b  = (const float*)d_in[8];
    const float* out_w  = (const float*)d_in[9];
    const float* out_b  = (const float*)d_in[10];
    const float* ln2_g  = (const float*)d_in[11];
    const float* ln2_b  = (const float*)d_in[12];
    const float* ff1_w  = (const float*)d_in[13];
    const float* ff1_b  = (const float*)d_in[14];
    const float* ff2_w  = (const float*)d_in[15];
    const float* ff2_b  = (const float*)d_in[16];
    float* outp = (float*)d_out;

    float *h, *y, *qb, *kb, *vb, *ob, *ff;
    cudaGetSymbolAddress((void**)&h,  g_h);
    cudaGetSymbolAddress((void**)&y,  g_y);
    cudaGetSymbolAddress((void**)&qb, g_q);
    cudaGetSymbolAddress((void**)&kb, g_k);
    cudaGetSymbolAddress((void**)&vb, g_v);
    cudaGetSymbolAddress((void**)&ob, g_o);
    cudaGetSymbolAddress((void**)&ff, g_ff);

    // input projection (x @ proj_w + proj_b) into y[0:8192]
    gemm_k<0><<<dim3(EDIM/128, MX/128), 256>>>(
        x, proj_w, proj_b, nullptr, y, MX, EDIM, EDIM, nullptr, nullptr, nullptr);
    // assemble token stream: cls + pos
    {
        long tot = (long)MTOT*EDIM;
        embed_k<<<(unsigned)((tot + 255)/256), 256>>>(y, cls, pos, h);
    }

    const int gy = (MTOT + 127)/128;   // 65
    for (int l = 0; l < NLAY; l++) {
        // LN1
        ln_k<<<MTOT, 256>>>(h, ln1_g + (long)l*EDIM, ln1_b + (long)l*EDIM, y);
        // QKV projection + head-interleave scatter
        gemm_k<3><<<dim3((3*EDIM)/128, gy), 256>>>(
            y, qkv_w + (long)l*EDIM*3*EDIM, qkv_b + (long)l*3*EDIM,
            nullptr, nullptr, MTOT, 3*EDIM, EDIM, qb, kb, vb);
        // fused attention (softmax exact, /sqrt(E) after softmax)
        attn_k<<<dim3(BSZ*NHEAD, (NTOK + 127)/128), 128>>>(qb, kb, vb, ob);
        // output projection + residual -> h
        gemm_k<1><<<dim3(EDIM/128, gy), 256>>>(
            ob, out_w + (long)l*EDIM*EDIM, out_b + (long)l*EDIM,
            h, h, MTOT, EDIM, EDIM, nullptr, nullptr, nullptr);
        // LN2
        ln_k<<<MTOT, 256>>>(h, ln2_g + (long)l*EDIM, ln2_b + (long)l*EDIM, y);
        // FF1 + exact GELU
        gemm_k<2><<<dim3(FFDIM/128, gy), 256>>>(
            y, ff1_w + (long)l*EDIM*FFDIM, ff1_b + (long)l*FFDIM,
            nullptr, ff, MTOT, FFDIM, EDIM, nullptr, nullptr, nullptr);
        // FF2 + residual -> h
        gemm_k<1><<<dim3(EDIM/128, gy), 256>>>(
            ff, ff2_w + (long)l*FFDIM*EDIM, ff2_b + (long)l*EDIM,
            h, h, MTOT, EDIM, FFDIM, nullptr, nullptr, nullptr);
    }

    out_k<<<(BSZ*EDIM + 255)/256, 256>>>(h, outp);
}

// round 3
// speedup vs baseline: 2.1275x; 2.1275x over previous
#include <cuda_runtime.h>
#include <cuda_bf16.h>
#include <cstdint>
#include <math.h>

// ---------------- problem constants ----------------
#define BSZ   16
#define NIN   512
#define NTOK  513
#define EDIM  768
#define NHEAD 12
#define HDIM  64
#define NLAY  12
#define FFDIM 3072
#define MTOT  (BSZ*NTOK)   // 8208
#define MX    (BSZ*NIN)    // 8192
#define MPAD  8320         // 65*128
#define KE    (3*EDIM)     // 2304  (K-extended: hi|lo|hi)
#define KF    (3*FFDIM)    // 9216
#define LNEPS 1e-5f
#define POSTSCALE 27.712812921102035f   // sqrt(768), applied AFTER softmax

typedef __nv_bfloat16 bf16;

// ---------------- scratch (static device globals; zero-initialized) -----
__device__ __align__(256) float g_h[(size_t)MTOT*EDIM];
__device__ __align__(256) float g_y[(size_t)MX*EDIM];
__device__ __align__(256) float g_q[(size_t)BSZ*NHEAD*NTOK*HDIM];
__device__ __align__(256) float g_k[(size_t)BSZ*NHEAD*NTOK*HDIM];
__device__ __align__(256) float g_v[(size_t)BSZ*NHEAD*NTOK*HDIM];
__device__ __align__(256) bf16 g_xe [(size_t)MX*KE];
__device__ __align__(256) bf16 g_ye [(size_t)MPAD*KE];
__device__ __align__(256) bf16 g_oe [(size_t)MPAD*KE];
__device__ __align__(256) bf16 g_ffe[(size_t)MPAD*KF];
__device__ __align__(256) bf16 g_wpe[(size_t)EDIM*KE];
__device__ __align__(256) bf16 g_wqe[(size_t)NLAY*3*EDIM*KE];
__device__ __align__(256) bf16 g_woe[(size_t)NLAY*EDIM*KE];
__device__ __align__(256) bf16 g_w1e[(size_t)NLAY*FFDIM*KE];
__device__ __align__(256) bf16 g_w2e[(size_t)NLAY*EDIM*KF];

// ---------------- small helpers ----------------
__device__ __forceinline__ uint32_t smem_u32(const void* p) {
    uint32_t a;
    asm("{ .reg .u64 t; cvta.to.shared.u64 t, %1; cvt.u32.u64 %0, t; }" : "=r"(a) : "l"(p));
    return a;
}
__device__ __forceinline__ void cp16(uint32_t sa, const void* g) {
    asm volatile("cp.async.cg.shared.global [%0], [%1], 16;" :: "r"(sa), "l"(g));
}
__device__ __forceinline__ void ldsm4(uint32_t& r0, uint32_t& r1, uint32_t& r2,
                                      uint32_t& r3, uint32_t addr) {
    asm volatile("ldmatrix.sync.aligned.m8n8.x4.shared.b16 {%0,%1,%2,%3}, [%4];"
                 : "=r"(r0), "=r"(r1), "=r"(r2), "=r"(r3) : "r"(addr));
}
__device__ __forceinline__ void mma16816(float* d, const uint32_t* a, const uint32_t* b) {
    asm volatile(
        "mma.sync.aligned.m16n8k16.row.col.f32.bf16.bf16.f32 "
        "{%0,%1,%2,%3}, {%4,%5,%6,%7}, {%8,%9}, {%0,%1,%2,%3};"
        : "+f"(d[0]), "+f"(d[1]), "+f"(d[2]), "+f"(d[3])
        : "r"(a[0]), "r"(a[1]), "r"(a[2]), "r"(a[3]), "r"(b[0]), "r"(b[1]));
}

// ---------------- weight convert + transpose: W[K,N] -> Wext[N,3K] -------
// Bext segments: [Bhi | Bhi | Blo]
__global__ void convw_k(const float* __restrict__ W, bf16* __restrict__ We,
                        int K, int N)
{
    long lay = blockIdx.z;
    W  += lay*(long)K*N;
    We += lay*(long)N*3*K;
    __shared__ float t[32][33];
    int tx = threadIdx.x, ty = threadIdx.y;
    int k0 = blockIdx.y*32, n0 = blockIdx.x*32;
    #pragma unroll
    for (int j = 0; j < 32; j += 8)
        t[ty+j][tx] = W[(long)(k0+ty+j)*N + n0+tx];
    __syncthreads();
    #pragma unroll
    for (int j = 0; j < 32; j += 8) {
        float v = t[tx][ty+j];                 // k = k0+tx, n = n0+ty+j
        long o = (long)(n0+ty+j)*3*K + k0 + tx;
        bf16 hi = __float2bfloat16(v);
        bf16 lo = __float2bfloat16(v - __bfloat162float(hi));
        We[o]       = hi;
        We[o + K]   = hi;
        We[o + 2*K] = lo;
    }
}

// ---------------- activation convert: X[M,K] -> Xext[M,3K] ---------------
// Aext segments: [Ahi | Alo | Ahi]
__global__ void convx_k(const float* __restrict__ X, bf16* __restrict__ Xe,
                        int K, long M)
{
    long i = (long)blockIdx.x*blockDim.x + threadIdx.x;
    if (i >= M*(long)K) return;
    long r = i / K; int k = (int)(i % K);
    float v = X[i];
    bf16 hi = __float2bfloat16(v);
    bf16 lo = __float2bfloat16(v - __bfloat162float(hi));
    long o = r*(long)(3*K) + k;
    Xe[o]       = hi;
    Xe[o + K]   = lo;
    Xe[o + 2*K] = hi;
}

// ================= bf16 mma.sync GEMM =================
// C[M,N] = Aext[M,Kext] @ Bext[N,Kext]^T, fp32 accumulate.
// EPI: 0 = bias -> fp32 R            1 = bias + residual accumulate into R
//      2 = bias + exact GELU -> ext bf16 Ce (segment stride = N)
//      3 = bias + qkv head scatter -> fp32 qb/kb/vb
#define TG_SMEM 65536
template<int EPI>
__global__ __launch_bounds__(256) void tgemm(
    const bf16* __restrict__ A, const bf16* __restrict__ B,
    const float* __restrict__ bias, float* __restrict__ R,
    bf16* __restrict__ Ce,
    float* __restrict__ qb, float* __restrict__ kb, float* __restrict__ vb,
    int M, int N, int Kext)
{
    extern __shared__ __align__(128) char sm[];
    uint32_t sA = smem_u32(sm);            // 2 x 16KB A stages
    uint32_t sB = sA + 32768;              // 2 x 16KB B stages

    const int tid  = threadIdx.x;
    const int lane = tid & 31;
    const int wid  = tid >> 5;
    const int wm   = wid & 1;              // 2 warps along M
    const int wn   = wid >> 1;             // 4 warps along N
    const long mbase = (long)blockIdx.y * 128;
    const long nbase = (long)blockIdx.x * 128;
    const bf16* Ag = A + mbase*(long)Kext;
    const bf16* Bg = B + nbase*(long)Kext;

    const int lrow = tid >> 3;             // 0..31
    const int lseg = tid & 7;              // 0..7 (16B segment)
    const int nst  = Kext >> 6;

    float acc[4][4][4];
    #pragma unroll
    for (int a = 0; a < 4; a++)
        #pragma unroll
        for (int b = 0; b < 4; b++)
            #pragma unroll
            for (int c = 0; c < 4; c++) acc[a][b][c] = 0.f;

    auto load_stage = [&](int s) {
        const int buf = s & 1;
        const uint32_t da = sA + buf*16384u;
        const uint32_t db = sB + buf*16384u;
        const long k0 = (long)s*64 + lseg*8;
        #pragma unroll
        for (int r4 = 0; r4 < 4; r4++) {
            int row = lrow + r4*32;
            uint32_t off = (uint32_t)row*128u + (uint32_t)((lseg*16) ^ ((row & 7) << 4));
            cp16(da + off, Ag + (long)row*Kext + k0);
            cp16(db + off, Bg + (long)row*Kext + k0);
        }
        asm volatile("cp.async.commit_group;");
    };

    load_stage(0);
    if (nst > 1) load_stage(1);

    const uint32_t xorA = (uint32_t)((lane & 7) << 4);
    for (int s = 0; s < nst; s++) {
        if (s + 1 < nst) asm volatile("cp.async.wait_group 1;" ::: "memory");
        else             asm volatile("cp.async.wait_group 0;" ::: "memory");
        __syncthreads();
        const uint32_t da = sA + (s & 1)*16384u;
        const uint32_t db = sB + (s & 1)*16384u;
        #pragma unroll
        for (int ks = 0; ks < 4; ks++) {
            uint32_t af[4][4], bfr[2][4];
            #pragma unroll
            for (int mt = 0; mt < 4; mt++) {
                int row = wm*64 + mt*16 + (lane & 15);
                uint32_t col = (uint32_t)(ks*32 + ((lane >> 4) << 4));
                ldsm4(af[mt][0], af[mt][1], af[mt][2], af[mt][3],
                      da + (uint32_t)row*128u + (col ^ xorA));
            }
            #pragma unroll
            for (int ng = 0; ng < 2; ng++) {
                int row = wn*32 + ng*16 + (lane & 7) + ((lane >> 4) << 3);
                uint32_t col = (uint32_t)(ks*32 + (((lane >> 3) & 1) << 4));
                ldsm4(bfr[ng][0], bfr[ng][1], bfr[ng][2], bfr[ng][3],
                      db + (uint32_t)row*128u + (col ^ xorA));
            }
            #pragma unroll
            for (int mt = 0; mt < 4; mt++)
                #pragma unroll
                for (int nt = 0; nt < 4; nt++)
                    mma16816(acc[mt][nt], af[mt], &bfr[nt >> 1][(nt & 1)*2]);
        }
        __syncthreads();
        if (s + 2 < nst) load_stage(s + 2);
    }

    // ---- epilogue (register layout: d0,d1 row t/4 cols 2(t%4)+{0,1};
    //                                 d2,d3 row t/4+8) ----
    #pragma unroll
    for (int mt = 0; mt < 4; mt++) {
        #pragma unroll
        for (int half = 0; half < 2; half++) {
            long r = mbase + wm*64 + mt*16 + (lane >> 2) + half*8;
            if (r >= M) continue;
            #pragma unroll
            for (int nt = 0; nt < 4; nt++) {
                int c = (int)nbase + wn*32 + nt*8 + ((lane & 3) << 1);
                float v0 = acc[mt][nt][half*2 + 0] + bias[c];
                float v1 = acc[mt][nt][half*2 + 1] + bias[c + 1];
                if (EPI == 0) {
                    R[r*(long)N + c]     = v0;
                    R[r*(long)N + c + 1] = v1;
                } else if (EPI == 1) {
                    long o = r*(long)N + c;
                    R[o]     += v0;
                    R[o + 1] += v1;
                } else if (EPI == 2) {
                    float g0 = 0.5f*v0*(1.0f + erff(v0*0.7071067811865475f));
                    float g1 = 0.5f*v1*(1.0f + erff(v1*0.7071067811865475f));
                    long o = r*(long)(3*N) + c;
                    bf16 h0 = __float2bfloat16(g0);
                    bf16 l0 = __float2bfloat16(g0 - __bfloat162float(h0));
                    bf16 h1 = __float2bfloat16(g1);
                    bf16 l1 = __float2bfloat16(g1 - __bfloat162float(h1));
                    Ce[o]           = h0; Ce[o + 1]         = h1;
                    Ce[o + N]       = l0; Ce[o + N + 1]     = l1;
                    Ce[o + 2*N]     = h0; Ce[o + 2*N + 1]   = h1;
                } else {
                    int bb = (int)(r / NTOK), n = (int)(r % NTOK);
                    #pragma unroll
                    for (int e2 = 0; e2 < 2; e2++) {
                        int cc = c + e2;
                        float val = (e2 ? v1 : v0);
                        int which = cc % 3;
                        int hh = cc / 192;
                        int dd = (cc / 3) & 63;
                        long off = ((long)(bb*NHEAD + hh)*NTOK + n)*HDIM + dd;
                        if (which == 0)      qb[off] = val;
                        else if (which == 1) kb[off] = val;
                        else                 vb[off] = val;
                    }
                }
            }
        }
    }
}

// ---------------- LayerNorm: fp32 in -> ext bf16 out (row len 3*EDIM) ----
__global__ __launch_bounds__(256) void ln_k(
    const float* __restrict__ x, const float* __restrict__ g,
    const float* __restrict__ b, bf16* __restrict__ ye)
{
    long row = blockIdx.x;
    const float* xr = x + row*(long)EDIM;
    int t = threadIdx.x;
    float v0 = xr[t], v1 = xr[t+256], v2 = xr[t+512];
    float s  = v0 + v1 + v2;
    float sq = v0*v0 + v1*v1 + v2*v2;
    #pragma unroll
    for (int o = 16; o > 0; o >>= 1) {
        s  += __shfl_xor_sync(0xffffffffu, s,  o);
        sq += __shfl_xor_sync(0xffffffffu, sq, o);
    }
    __shared__ float ss[8], sqs[8];
    __shared__ float mu_s, rs_s;
    if ((t & 31) == 0) { ss[t>>5] = s; sqs[t>>5] = sq; }
    __syncthreads();
    if (t == 0) {
        float S = 0.f, Q = 0.f;
        #pragma unroll
        for (int i = 0; i < 8; i++) { S += ss[i]; Q += sqs[i]; }
        float mu = S * (1.0f/EDIM);
        float var = Q * (1.0f/EDIM) - mu*mu;
        mu_s = mu;
        rs_s = rsqrtf(var + LNEPS);
    }
    __syncthreads();
    float mu = mu_s, rs = rs_s;
    long base = row*(long)KE;
    #pragma unroll
    for (int pp = 0; pp < 3; pp++) {
        int e = t + pp*256;
        float vv = (pp == 0 ? v0 : pp == 1 ? v1 : v2);
        float o = (vv - mu)*rs*g[e] + b[e];
        bf16 hi = __float2bfloat16(o);
        bf16 lo = __float2bfloat16(o - __bfloat162float(hi));
        ye[base + e]          = hi;
        ye[base + EDIM + e]   = lo;
        ye[base + 2*EDIM + e] = hi;
    }
}

// ---------------- fused attention (fp32 SIMT) -> ext bf16 out ------------
__global__ __launch_bounds__(128) void attn_k(
    const float* __restrict__ q, const float* __restrict__ k,
    const float* __restrict__ v, bf16* __restrict__ oe)
{
    const int bh = blockIdx.x;
    const int qi = blockIdx.y*128 + threadIdx.x;
    const int b = bh / NHEAD, hh = bh % NHEAD;
    const long base = (long)bh*NTOK*HDIM;
    const bool act = (qi < NTOK);
    const int tid = threadIdx.x;

    float qr[64];
    if (act) {
        const float4* qp = (const float4*)(q + base + (long)qi*HDIM);
        #pragma unroll
        for (int i = 0; i < 16; i++) {
            float4 t4 = qp[i];
            qr[4*i] = t4.x; qr[4*i+1] = t4.y; qr[4*i+2] = t4.z; qr[4*i+3] = t4.w;
        }
    }
    float m = -3.0e38f, l = 0.f, acc[64];
    #pragma unroll
    for (int d = 0; d < 64; d++) acc[d] = 0.f;

    __shared__ float Ks[32][64];
    __shared__ float Vs[32][64];

    for (int kb = 0; kb < NTOK; kb += 32) {
        int nk = NTOK - kb; if (nk > 32) nk = 32;
        __syncthreads();
        #pragma unroll
        for (int i = 0; i < 4; i++) {
            int idx = i*512 + tid*4;
            int row = idx >> 6, col = idx & 63;
            if (row < nk) {
                *(float4*)&Ks[row][col] = *(const float4*)(k + base + (long)(kb+row)*HDIM + col);
                *(float4*)&Vs[row][col] = *(const float4*)(v + base + (long)(kb+row)*HDIM + col);
            }
        }
        __syncthreads();
        if (act) {
            for (int kk = 0; kk < nk; kk++) {
                float s = 0.f;
                #pragma unroll
                for (int d = 0; d < 64; d++) s = fmaf(qr[d], Ks[kk][d], s);
                if (s > m) {
                    float c = __expf(m - s);
                    l = l*c + 1.f;
                    #pragma unroll
                    for (int d = 0; d < 64; d++) acc[d] = acc[d]*c + Vs[kk][d];
                    m = s;
                } else {
                    float e = __expf(s - m);
                    l += e;
                    #pragma unroll
                    for (int d = 0; d < 64; d++) acc[d] = fmaf(e, Vs[kk][d], acc[d]);
                }
            }
        }
    }
    if (act) {
        float inv = 1.f / (l * POSTSCALE);
        long ob = ((long)(b*NTOK) + qi)*KE + hh*HDIM;
        #pragma unroll
        for (int d = 0; d < 64; d++) {
            float o = acc[d]*inv;
            bf16 hi = __float2bfloat16(o);
            bf16 lo = __float2bfloat16(o - __bfloat162float(hi));
            oe[ob + d]          = hi;
            oe[ob + EDIM + d]   = lo;
            oe[ob + 2*EDIM + d] = hi;
        }
    }
}

// ---------------- embed ----------------
__global__ void embed_k(const float* __restrict__ t, const float* __restrict__ cls,
                        const float* __restrict__ pos, float* __restrict__ h)
{
    long idx = (long)blockIdx.x*blockDim.x + threadIdx.x;
    if (idx >= (long)MTOT*EDIM) return;
    int e = (int)(idx % EDIM);
    long row = idx / EDIM;
    int b = (int)(row / NTOK), n = (int)(row % NTOK);
    float base = (n == 0) ? cls[e] : t[((long)b*NIN + (n-1))*EDIM + e];
    h[idx] = base + pos[(long)n*EDIM + e];
}

// ---------------- output: CLS rows ----------------
__global__ void out_k(const float* __restrict__ h, float* __restrict__ out)
{
    int i = blockIdx.x*blockDim.x + threadIdx.x;
    if (i >= BSZ*EDIM) return;
    int b = i / EDIM, e = i % EDIM;
    out[i] = h[(long)b*NTOK*EDIM + e];
}

// ---------------- host launcher ----------------
extern "C" void kernel_launch(void* const* d_in, const int* in_sizes, int n_in,
                              void* d_out, int out_size)
{
    const float* x      = (const float*)d_in[0];
    const float* proj_w = (const float*)d_in[1];
    const float* proj_b = (const float*)d_in[2];
    const float* cls    = (const float*)d_in[3];
    const float* pos    = (const float*)d_in[4];
    const float* ln1_g  = (const float*)d_in[5];
    const float* ln1_b  = (const float*)d_in[6];
    const float* qkv_w  = (const float*)d_in[7];
    const float* qkv_b  = (const float*)d_in[8];
    const float* out_w  = (const float*)d_in[9];
    const float* out_b  = (const float*)d_in[10];
    const float* ln2_g  = (const float*)d_in[11];
    const float* ln2_b  = (const float*)d_in[12];
    const float* ff1_w  = (const float*)d_in[13];
    const float* ff1_b  = (const float*)d_in[14];
    const float* ff2_w  = (const float*)d_in[15];
    const float* ff2_b  = (const float*)d_in[16];
    float* outp = (float*)d_out;

    float *h, *y, *qb, *kb, *vb;
    bf16 *xe, *ye, *oe, *ffe, *wpe, *wqe, *woe, *w1e, *w2e;
    cudaGetSymbolAddress((void**)&h,   g_h);
    cudaGetSymbolAddress((void**)&y,   g_y);
    cudaGetSymbolAddress((void**)&qb,  g_q);
    cudaGetSymbolAddress((void**)&kb,  g_k);
    cudaGetSymbolAddress((void**)&vb,  g_v);
    cudaGetSymbolAddress((void**)&xe,  g_xe);
    cudaGetSymbolAddress((void**)&ye,  g_ye);
    cudaGetSymbolAddress((void**)&oe,  g_oe);
    cudaGetSymbolAddress((void**)&ffe, g_ffe);
    cudaGetSymbolAddress((void**)&wpe, g_wpe);
    cudaGetSymbolAddress((void**)&wqe, g_wqe);
    cudaGetSymbolAddress((void**)&woe, g_woe);
    cudaGetSymbolAddress((void**)&w1e, g_w1e);
    cudaGetSymbolAddress((void**)&w2e, g_w2e);

    cudaFuncSetAttribute(tgemm<0>, cudaFuncAttributeMaxDynamicSharedMemorySize, TG_SMEM);
    cudaFuncSetAttribute(tgemm<1>, cudaFuncAttributeMaxDynamicSharedMemorySize, TG_SMEM);
    cudaFuncSetAttribute(tgemm<2>, cudaFuncAttributeMaxDynamicSharedMemorySize, TG_SMEM);
    cudaFuncSetAttribute(tgemm<3>, cudaFuncAttributeMaxDynamicSharedMemorySize, TG_SMEM);

    dim3 cw(32, 8);
    // weight conversions (transpose + bf16 split, K-extended layout)
    convw_k<<<dim3(EDIM/32,   EDIM/32,  1),    cw>>>(proj_w, wpe, EDIM,  EDIM);
    convw_k<<<dim3(3*EDIM/32, EDIM/32,  NLAY), cw>>>(qkv_w,  wqe, EDIM,  3*EDIM);
    convw_k<<<dim3(EDIM/32,   EDIM/32,  NLAY), cw>>>(out_w,  woe, EDIM,  EDIM);
    convw_k<<<dim3(FFDIM/32,  EDIM/32,  NLAY), cw>>>(ff1_w,  w1e, EDIM,  FFDIM);
    convw_k<<<dim3(EDIM/32,   FFDIM/32, NLAY), cw>>>(ff2_w,  w2e, FFDIM, EDIM);
    // input conversion
    {
        long n = (long)MX*EDIM;
        convx_k<<<(unsigned)((n + 255)/256), 256>>>(x, xe, EDIM, MX);
    }

    // input projection -> y (fp32)
    tgemm<0><<<dim3(EDIM/128, MX/128), 256, TG_SMEM>>>(
        xe, wpe, proj_b, y, nullptr, nullptr, nullptr, nullptr, MX, EDIM, KE);
    {
        long tot = (long)MTOT*EDIM;
        embed_k<<<(unsigned)((tot + 255)/256), 256>>>(y, cls, pos, h);
    }

    const int gy = (MTOT + 127)/128;   // 65
    for (int l = 0; l < NLAY; l++) {
        ln_k<<<MTOT, 256>>>(h, ln1_g + (long)l*EDIM, ln1_b + (long)l*EDIM, ye);
        tgemm<3><<<dim3(3*EDIM/128, gy), 256, TG_SMEM>>>(
            ye, wqe + (long)l*3*EDIM*KE, qkv_b + (long)l*3*EDIM,
            nullptr, nullptr, qb, kb, vb, MTOT, 3*EDIM, KE);
        attn_k<<<dim3(BSZ*NHEAD, (NTOK + 127)/128), 128>>>(qb, kb, vb, oe);
        tgemm<1><<<dim3(EDIM/128, gy), 256, TG_SMEM>>>(
            oe, woe + (long)l*EDIM*KE, out_b + (long)l*EDIM,
            h, nullptr, nullptr, nullptr, nullptr, MTOT, EDIM, KE);
        ln_k<<<MTOT, 256>>>(h, ln2_g + (long)l*EDIM, ln2_b + (long)l*EDIM, ye);
        tgemm<2><<<dim3(FFDIM/128, gy), 256, TG_SMEM>>>(
            ye, w1e + (long)l*FFDIM*KE, ff1_b + (long)l*FFDIM,
            nullptr, ffe, nullptr, nullptr, nullptr, MTOT, FFDIM, KE);
        tgemm<1><<<dim3(EDIM/128, gy), 256, TG_SMEM>>>(
            ffe, w2e + (long)l*EDIM*KF, ff2_b + (long)l*EDIM,
            h, nullptr, nullptr, nullptr, nullptr, MTOT, EDIM, KF);
    }

    out_k<<<(BSZ*EDIM + 255)/256, 256>>>(h, outp);
}